// round 16
// baseline (speedup 1.0000x reference)
#include <cuda_runtime.h>
#include <cuda_bf16.h>
#include <math.h>

// Problem constants
#define BATCH 4
#define SEQ   1024
#define DMODEL 1024
#define HEADS 16
#define DK    64

// Scratch (device globals: allocation-free rule)
__device__ float g_Q[BATCH * HEADS * SEQ * DK];   // [b,h,n,d]  tf32-rounded, d pi-permuted
__device__ float g_K[BATCH * HEADS * SEQ * DK];
__device__ float g_V[BATCH * HEADS * SEQ * DK];
__device__ float g_O[BATCH * SEQ * DMODEL];       // [b,n,D] attention output (tf32-rounded)
__device__ float g_Xr[BATCH * SEQ * DMODEL];      // X rounded to tf32
__device__ float g_Wr[4 * DMODEL * DMODEL];       // Wq,Wk,Wv,Wo rounded to tf32

// ---------------------------------------------------------------------------
// tf32 + cp.async helpers
// ---------------------------------------------------------------------------
__device__ __forceinline__ unsigned int f2tf32(float x) {
    unsigned int u;
    asm("cvt.rna.tf32.f32 %0, %1;" : "=r"(u) : "f"(x));
    return u;
}
__device__ __forceinline__ float tf32f(float x) {
    return __uint_as_float(f2tf32(x));
}

__device__ __forceinline__ void mma_tf32(float c[4],
                                         unsigned int a0, unsigned int a1,
                                         unsigned int a2, unsigned int a3,
                                         unsigned int b0, unsigned int b1) {
    asm volatile(
        "mma.sync.aligned.m16n8k8.row.col.f32.tf32.tf32.f32 "
        "{%0,%1,%2,%3}, {%4,%5,%6,%7}, {%8,%9}, {%0,%1,%2,%3};\n"
        : "+f"(c[0]), "+f"(c[1]), "+f"(c[2]), "+f"(c[3])
        : "r"(a0), "r"(a1), "r"(a2), "r"(a3), "r"(b0), "r"(b1));
}

__device__ __forceinline__ void cp16(void* smem_dst, const void* gsrc) {
    unsigned int s = (unsigned int)__cvta_generic_to_shared(smem_dst);
    asm volatile("cp.async.cg.shared.global [%0], [%1], 16;\n" :: "r"(s), "l"(gsrc));
}
#define CP_COMMIT() asm volatile("cp.async.commit_group;\n" ::)
#define CP_WAIT1()  asm volatile("cp.async.wait_group 1;\n" ::)

// ---------------------------------------------------------------------------
// Rounding kernels: X and W* -> tf32 once (staging becomes raw byte copy)
// ---------------------------------------------------------------------------
__global__ void round_x_kernel(const float* __restrict__ X) {
    int i = blockIdx.x * blockDim.x + threadIdx.x;
    float4 v = ((const float4*)X)[i];
    v.x = tf32f(v.x); v.y = tf32f(v.y); v.z = tf32f(v.z); v.w = tf32f(v.w);
    ((float4*)g_Xr)[i] = v;
}

__global__ void round_w_kernel(const float* __restrict__ w0, const float* __restrict__ w1,
                               const float* __restrict__ w2, const float* __restrict__ w3) {
    int i = blockIdx.x * blockDim.x + threadIdx.x;
    int sel = i >> 18;
    int off = i & 262143;
    const float* src = (sel == 0) ? w0 : (sel == 1) ? w1 : (sel == 2) ? w2 : w3;
    float4 v = ((const float4*)src)[off];
    v.x = tf32f(v.x); v.y = tf32f(v.y); v.z = tf32f(v.z); v.w = tf32f(v.w);
    ((float4*)g_Wr)[i] = v;
}

// ---------------------------------------------------------------------------
// tf32 GEMM v3 (unchanged from R15, which passed): TBK=32, 2-stage cp.async,
// QKV fusion over blockIdx.z, dynamic smem.
// ---------------------------------------------------------------------------
#define TBM 128
#define TBN 128
#define TBK 32
#define AST 36
#define BST 136
#define GAS (TBM * AST)
#define GBS (TBK * BST)
#define GEMM_SMEM_BYTES ((2 * GAS + 2 * GBS) * 4)   // 71680 B

__global__ __launch_bounds__(256, 2)
void tf32_gemm3_kernel(const float* __restrict__ A,
                       const float* __restrict__ Wbase,
                       const float* __restrict__ bias0,
                       const float* __restrict__ bias1,
                       const float* __restrict__ bias2,
                       float* __restrict__ out,
                       int qkvMode)
{
    extern __shared__ __align__(16) float gsm[];
    float* AsB = gsm;
    float* BsB = gsm + 2 * GAS;

    const int z  = blockIdx.z;
    const float* W    = Wbase + (size_t)z * DMODEL * DMODEL;
    const float* bias = (z == 0) ? bias0 : (z == 1) ? bias1 : bias2;

    const int m0 = blockIdx.y * TBM;
    const int n0 = blockIdx.x * TBN;
    const int tid = threadIdx.x;
    const int wid = tid >> 5;
    const int lane = tid & 31;
    const int wm = wid >> 2;
    const int wn = wid & 3;
    const int gid = lane >> 2;
    const int tig = lane & 3;

    float c[4][4][4];
#pragma unroll
    for (int i = 0; i < 4; i++)
#pragma unroll
        for (int j = 0; j < 4; j++)
#pragma unroll
            for (int r = 0; r < 4; r++) c[i][j][r] = 0.0f;

#define GEMM_STAGE(buf, tidx) do {                                             \
        int k0s = (tidx) * TBK;                                                \
        float* Asb = AsB + (buf) * GAS;                                        \
        float* Bsb = BsB + (buf) * GBS;                                        \
        _Pragma("unroll")                                                      \
        for (int q = 0; q < 4; q++) {                                          \
            int cch = q * 256 + tid;                                           \
            int row = cch >> 3, sg = (cch & 7) << 2;                           \
            cp16(&Asb[row * AST + sg],                                         \
                 A + (size_t)(m0 + row) * DMODEL + k0s + sg);                  \
        }                                                                      \
        _Pragma("unroll")                                                      \
        for (int q = 0; q < 4; q++) {                                          \
            int cch = q * 256 + tid;                                           \
            int kk = cch >> 5, cs = (cch & 31) << 2;                           \
            cp16(&Bsb[kk * BST + cs],                                          \
                 W + (size_t)(k0s + kk) * DMODEL + n0 + cs);                   \
        }                                                                      \
    } while (0)

    GEMM_STAGE(0, 0);
    CP_COMMIT();

    for (int t = 0; t < DMODEL / TBK; t++) {
        int buf = t & 1;
        if (t < DMODEL / TBK - 1) GEMM_STAGE(buf ^ 1, t + 1);
        CP_COMMIT();
        CP_WAIT1();
        __syncthreads();

        const float* Asb = AsB + buf * GAS;
        const float* Bsb = BsB + buf * GBS;

#pragma unroll
        for (int ks = 0; ks < 4; ks++) {
            const int kb = ks * 8;
            unsigned int af[4][4], bf[4][2];
#pragma unroll
            for (int i = 0; i < 4; i++) {
                int mb = wm * 64 + i * 16;
                af[i][0] = __float_as_uint(Asb[(mb + gid    ) * AST + kb + tig]);
                af[i][1] = __float_as_uint(Asb[(mb + gid + 8) * AST + kb + tig]);
                af[i][2] = __float_as_uint(Asb[(mb + gid    ) * AST + kb + tig + 4]);
                af[i][3] = __float_as_uint(Asb[(mb + gid + 8) * AST + kb + tig + 4]);
            }
#pragma unroll
            for (int j = 0; j < 4; j++) {
                int nb = wn * 32 + j * 8;
                bf[j][0] = __float_as_uint(Bsb[(kb + tig    ) * BST + nb + gid]);
                bf[j][1] = __float_as_uint(Bsb[(kb + tig + 4) * BST + nb + gid]);
            }
#pragma unroll
            for (int i = 0; i < 4; i++)
#pragma unroll
                for (int j = 0; j < 4; j++)
                    mma_tf32(c[i][j], af[i][0], af[i][1], af[i][2], af[i][3],
                             bf[j][0], bf[j][1]);
        }
        __syncthreads();
    }
#undef GEMM_STAGE

    float* dst = out;
    if (qkvMode) dst = (z == 0) ? g_Q : (z == 1) ? g_K : g_V;

#pragma unroll
    for (int i = 0; i < 4; i++) {
        int r0 = m0 + wm * 64 + i * 16 + gid;
        int r1 = r0 + 8;
#pragma unroll
        for (int j = 0; j < 4; j++) {
            int cb = n0 + wn * 32 + j * 8 + 2 * tig;
#pragma unroll
            for (int e = 0; e < 2; e++) {
                int cc = cb + e;
                float v0 = c[i][j][e]     + bias[cc];
                float v1 = c[i][j][e + 2] + bias[cc];
                if (qkvMode) {
                    int h = cc >> 6, d = cc & 63;
                    int d2 = (d & 56) | (2 * (d & 3) + ((d & 7) >> 2));
                    int b0i = r0 >> 10, n0i = r0 & 1023;
                    int b1i = r1 >> 10, n1i = r1 & 1023;
                    dst[(size_t)(b0i * HEADS + h) * (SEQ * DK) + (size_t)n0i * DK + d2] = tf32f(v0);
                    dst[(size_t)(b1i * HEADS + h) * (SEQ * DK) + (size_t)n1i * DK + d2] = tf32f(v1);
                } else {
                    dst[(size_t)r0 * DMODEL + cc] = v0;
                    dst[(size_t)r1 * DMODEL + cc] = v1;
                }
            }
        }
    }
}

// ---------------------------------------------------------------------------
// Tensor-core flash attention v4: 512 threads, 16 warps as 8(m) x 2(n).
// CTA tile 128q x 64k; warp tile 16x32. Same smem layout / pi layout /
// cp.async pipeline as v3; doubled warp count for latency hiding.
// ---------------------------------------------------------------------------
#define AT 72
#define SQ_OFF   0
#define SK_OFF   (128 * AT)
#define SV_OFF   (SK_OFF + 2 * 64 * AT)
#define SP_OFF   (SV_OFF + 2 * 64 * AT)
#define SMAX_OFF (SP_OFF + 2 * 128 * AT)
#define SSUM_OFF (SMAX_OFF + 256)
#define SMSK_OFF (SSUM_OFF + 256)
#define ATTN_SMEM_BYTES ((SMSK_OFF + 1024) * 4)   // 190464 B

__global__ __launch_bounds__(512, 1)
void attn_tc4_kernel(const float* __restrict__ Bij,
                     const unsigned int* __restrict__ maskW)
{
    extern __shared__ float sm[];
    float* sMax = sm + SMAX_OFF;
    float* sSum = sm + SSUM_OFF;
    unsigned int* sMsk = (unsigned int*)(sm + SMSK_OFF);

    const int b  = blockIdx.z;
    const int h  = blockIdx.y;
    const int q0 = blockIdx.x * 128;
    const int tid  = threadIdx.x;
    const int lane = tid & 31;
    const int wid  = tid >> 5;
    const int wm = wid >> 1;          // 0..7  (16-row m block)
    const int wn = wid & 1;           // 0..1  (32-col n block)
    const int gid = lane >> 2;        // 0..7
    const int tig = lane & 3;         // 0..3
    const int bh = b * HEADS + h;
    const float scale = 0.125f;

    const int pg  = 2 * (gid & 3) + (gid >> 2);
    const int pu0 = 2 * ((2 * tig) & 3) + ((2 * tig) >> 2);
    const int pu1 = 2 * ((2 * tig + 1) & 3) + ((2 * tig + 1) >> 2);

    const int r0 = wm * 16 + gid;     // thread's 2 q-rows
    const int r1 = r0 + 8;

    const float* Qg = g_Q + (size_t)(bh * SEQ + q0) * DK;
    const float* Kg = g_K + (size_t)bh * SEQ * DK;
    const float* Vg = g_V + (size_t)bh * SEQ * DK;
    const float* Bg = Bij + ((size_t)bh * SEQ + q0) * SEQ;

    // stage: K/V 64x64 (2x512 chunks each), bias 128x64 (4x512 chunks)
#define ATTN_STAGE(buf, kt) do {                                               \
        float* sKb = sm + SK_OFF + (buf) * 64 * AT;                            \
        float* sVb = sm + SV_OFF + (buf) * 64 * AT;                            \
        float* sPb = sm + SP_OFF + (buf) * 128 * AT;                           \
        const float* Kt = Kg + (size_t)(kt) * 64 * DK;                         \
        const float* Vt = Vg + (size_t)(kt) * 64 * DK;                         \
        const float* Bt = Bg + (kt) * 64;                                      \
        _Pragma("unroll")                                                      \
        for (int t = 0; t < 2; t++) {                                          \
            int cch = t * 512 + tid;                                           \
            int row = cch >> 4, col = (cch & 15) << 2;                         \
            cp16(&sKb[row * AT + col], Kt + row * DK + col);                   \
            cp16(&sVb[row * AT + col], Vt + row * DK + col);                   \
        }                                                                      \
        _Pragma("unroll")                                                      \
        for (int t = 0; t < 4; t++) {                                          \
            int cch = t * 512 + tid;                                           \
            int row = cch >> 4, col = (cch & 15) << 2;                         \
            cp16(&sPb[row * AT + col], Bt + (size_t)row * SEQ + col);          \
        }                                                                      \
    } while (0)

    // Prologue: Q (128x64), mask (1024 words), tile 0
    {
#pragma unroll
        for (int t = 0; t < 4; t++) {
            int cch = t * 512 + tid;
            int row = cch >> 4, col = (cch & 15) << 2;
            cp16(&sm[SQ_OFF + row * AT + col], Qg + (size_t)row * DK + col);
        }
        if (tid < 256) cp16(&sMsk[tid * 4], maskW + (size_t)b * SEQ + tid * 4);
        ATTN_STAGE(0, 0);
        CP_COMMIT();
    }

    float mI0 = -INFINITY, mI1 = -INFINITY, lI0 = 0.0f, lI1 = 0.0f;
    float o[4][4];
#pragma unroll
    for (int j = 0; j < 4; j++)
#pragma unroll
        for (int r = 0; r < 4; r++) o[j][r] = 0.0f;

    for (int kt = 0; kt < SEQ / 64; kt++) {
        const int buf = kt & 1;
        const int k0c = kt * 64;
        float* sKb = sm + SK_OFF + buf * 64 * AT;
        float* sVb = sm + SV_OFF + buf * 64 * AT;
        float* sPb = sm + SP_OFF + buf * 128 * AT;

        if (kt + 1 < SEQ / 64) ATTN_STAGE(buf ^ 1, kt + 1);
        CP_COMMIT();
        CP_WAIT1();
        __syncthreads();

        // ---- S = Q K^T : warp 16x32 ----
        float c[4][4];
#pragma unroll
        for (int j = 0; j < 4; j++)
#pragma unroll
            for (int r = 0; r < 4; r++) c[j][r] = 0.0f;

#pragma unroll
        for (int kb = 0; kb < 64; kb += 8) {
            float2 qa0 = *(float2*)&sm[SQ_OFF + r0 * AT + kb + 2 * tig];
            float2 qa1 = *(float2*)&sm[SQ_OFF + r1 * AT + kb + 2 * tig];
            unsigned int a0 = __float_as_uint(qa0.x);
            unsigned int a1 = __float_as_uint(qa1.x);
            unsigned int a2 = __float_as_uint(qa0.y);
            unsigned int a3 = __float_as_uint(qa1.y);
#pragma unroll
            for (int j = 0; j < 4; j++) {
                int key = wn * 32 + j * 8 + gid;
                float2 kf = *(float2*)&sKb[key * AT + kb + 2 * tig];
                mma_tf32(c[j], a0, a1, a2, a3,
                         __float_as_uint(kf.x), __float_as_uint(kf.y));
            }
        }

        // ---- scale + bias + mask; per-row partial max ----
        float pm0 = -INFINITY, pm1 = -INFINITY;
#pragma unroll
        for (int j = 0; j < 4; j++) {
            int cc0 = wn * 32 + j * 8 + 2 * tig;
            int cc1 = cc0 + 1;
            bool mk0 = sMsk[k0c + cc0] != 0u;
            bool mk1 = sMsk[k0c + cc1] != 0u;
            float v0 = mk0 ? fmaf(c[j][0], scale, sPb[r0 * AT + cc0]) : -10000.0f;
            float v1 = mk1 ? fmaf(c[j][1], scale, sPb[r0 * AT + cc1]) : -10000.0f;
            float v2 = mk0 ? fmaf(c[j][2], scale, sPb[r1 * AT + cc0]) : -10000.0f;
            float v3 = mk1 ? fmaf(c[j][3], scale, sPb[r1 * AT + cc1]) : -10000.0f;
            c[j][0] = v0; c[j][1] = v1; c[j][2] = v2; c[j][3] = v3;
            pm0 = fmaxf(pm0, fmaxf(v0, v1));
            pm1 = fmaxf(pm1, fmaxf(v2, v3));
        }
        pm0 = fmaxf(pm0, __shfl_xor_sync(0xffffffffu, pm0, 1));
        pm0 = fmaxf(pm0, __shfl_xor_sync(0xffffffffu, pm0, 2));
        pm1 = fmaxf(pm1, __shfl_xor_sync(0xffffffffu, pm1, 1));
        pm1 = fmaxf(pm1, __shfl_xor_sync(0xffffffffu, pm1, 2));
        if (tig == 0) { sMax[r0 * 2 + wn] = pm0; sMax[r1 * 2 + wn] = pm1; }
        __syncthreads();

        float mN0 = fmaxf(mI0, fmaxf(sMax[r0 * 2], sMax[r0 * 2 + 1]));
        float mN1 = fmaxf(mI1, fmaxf(sMax[r1 * 2], sMax[r1 * 2 + 1]));
        float al0 = __expf(mI0 - mN0);
        float al1 = __expf(mI1 - mN1);
        mI0 = mN0; mI1 = mN1;

        // exp + write P (tf32, pi cols)
        float ps0 = 0.0f, ps1 = 0.0f;
#pragma unroll
        for (int j = 0; j < 4; j++) {
            int base0 = r0 * AT + wn * 32 + j * 8;
            int base1 = r1 * AT + wn * 32 + j * 8;
            float p0 = __expf(c[j][0] - mN0);
            float p1 = __expf(c[j][1] - mN0);
            float p2 = __expf(c[j][2] - mN1);
            float p3 = __expf(c[j][3] - mN1);
            sPb[base0 + pu0] = tf32f(p0);
            sPb[base0 + pu1] = tf32f(p1);
            sPb[base1 + pu0] = tf32f(p2);
            sPb[base1 + pu1] = tf32f(p3);
            ps0 += p0 + p1;
            ps1 += p2 + p3;
        }
        ps0 += __shfl_xor_sync(0xffffffffu, ps0, 1);
        ps0 += __shfl_xor_sync(0xffffffffu, ps0, 2);
        ps1 += __shfl_xor_sync(0xffffffffu, ps1, 1);
        ps1 += __shfl_xor_sync(0xffffffffu, ps1, 2);
        if (tig == 0) { sSum[r0 * 2 + wn] = ps0; sSum[r1 * 2 + wn] = ps1; }

        // rescale O accumulators
#pragma unroll
        for (int j = 0; j < 4; j++) {
            o[j][0] *= al0; o[j][1] *= al0;
            o[j][2] *= al1; o[j][3] *= al1;
        }
        __syncthreads();

        lI0 = lI0 * al0 + sSum[r0 * 2] + sSum[r0 * 2 + 1];
        lI1 = lI1 * al1 + sSum[r1 * 2] + sSum[r1 * 2 + 1];

        // ---- O += P V ----
#pragma unroll
        for (int kb = 0; kb < 64; kb += 8) {
            float2 pa0 = *(float2*)&sPb[r0 * AT + kb + 2 * tig];
            float2 pa1 = *(float2*)&sPb[r1 * AT + kb + 2 * tig];
            unsigned int a0 = __float_as_uint(pa0.x);
            unsigned int a1 = __float_as_uint(pa1.x);
            unsigned int a2 = __float_as_uint(pa0.y);
            unsigned int a3 = __float_as_uint(pa1.y);
#pragma unroll
            for (int j = 0; j < 4; j++) {
                int dcol = wn * 32 + j * 8 + pg;
                unsigned int b0 = __float_as_uint(sVb[(kb + tig)     * AT + dcol]);
                unsigned int b1 = __float_as_uint(sVb[(kb + tig + 4) * AT + dcol]);
                mma_tf32(o[j], a0, a1, a2, a3, b0, b1);
            }
        }
        __syncthreads();   // release buf before next prefetch overwrites it
    }
#undef ATTN_STAGE

    // Epilogue: write [b, q0+row, h*64 + d], tf32-rounded for final GEMM
    float inv0 = 1.0f / lI0;
    float inv1 = 1.0f / lI1;
    float* Og = g_O + ((size_t)b * SEQ + q0) * DMODEL + h * DK;
#pragma unroll
    for (int j = 0; j < 4; j++) {
#pragma unroll
        for (int e = 0; e < 2; e++) {
            int cc = wn * 32 + j * 8 + 2 * tig + e;
            Og[(size_t)r0 * DMODEL + cc] = tf32f(o[j][e]     * inv0);
            Og[(size_t)r1 * DMODEL + cc] = tf32f(o[j][e + 2] * inv1);
        }
    }
}

// ---------------------------------------------------------------------------
extern "C" void kernel_launch(void* const* d_in, const int* in_sizes, int n_in,
                              void* d_out, int out_size)
{
    // Identify inputs by element count (robust to metadata ordering)
    const float* X = 0; const float* Bij = 0; const void* maskP = 0;
    const float* Ws[4] = {0, 0, 0, 0};
    const float* bs[4] = {0, 0, 0, 0};
    int nW = 0, nB = 0;
    for (int i = 0; i < n_in; i++) {
        int sz = in_sizes[i];
        if (sz == BATCH * HEADS * SEQ * SEQ)      Bij  = (const float*)d_in[i];
        else if (sz == BATCH * SEQ * DMODEL)      X    = (const float*)d_in[i];
        else if (sz == BATCH * SEQ)               maskP = d_in[i];
        else if (sz == DMODEL * DMODEL && nW < 4) Ws[nW++] = (const float*)d_in[i];
        else if (sz == DMODEL && nB < 4)          bs[nB++] = (const float*)d_in[i];
    }
    const float *Wq = Ws[0], *Wk = Ws[1], *Wv = Ws[2], *Wo = Ws[3];
    const float *bq = bs[0], *bk = bs[1], *bv = bs[2], *bo = bs[3];
    float* out = (float*)d_out;

    float *op, *xr, *wr;
    cudaGetSymbolAddress((void**)&op, g_O);
    cudaGetSymbolAddress((void**)&xr, g_Xr);
    cudaGetSymbolAddress((void**)&wr, g_Wr);

    cudaFuncSetAttribute(attn_tc4_kernel, cudaFuncAttributeMaxDynamicSharedMemorySize,
                         ATTN_SMEM_BYTES);
    cudaFuncSetAttribute(tf32_gemm3_kernel, cudaFuncAttributeMaxDynamicSharedMemorySize,
                         GEMM_SMEM_BYTES);

    // Pre-round X and weights to tf32
    round_x_kernel<<<4096, 256>>>(X);
    round_w_kernel<<<4096, 256>>>(Wq, Wk, Wv, Wo);

    const int WSZ = DMODEL * DMODEL;

    // Fused QKV: grid.z = 3 selects W/bias/destination
    dim3 gQKV(DMODEL / TBN, (BATCH * SEQ) / TBM, 3);   // (8, 32, 3)
    tf32_gemm3_kernel<<<gQKV, 256, GEMM_SMEM_BYTES>>>(xr, wr, bq, bk, bv, 0, 1);

    dim3 gAttn(SEQ / 128, HEADS, BATCH);               // (8, 16, 4)
    attn_tc4_kernel<<<gAttn, 512, ATTN_SMEM_BYTES>>>(Bij, (const unsigned int*)maskP);

    // Output projection (z=0 only)
    dim3 gO(DMODEL / TBN, (BATCH * SEQ) / TBM, 1);
    tf32_gemm3_kernel<<<gO, 256, GEMM_SMEM_BYTES>>>(op, wr + 3 * WSZ, bo, bo, bo, out, 0);
}

// round 17
// speedup vs baseline: 1.0743x; 1.0743x over previous
#include <cuda_runtime.h>
#include <cuda_bf16.h>
#include <math.h>

// Problem constants
#define BATCH 4
#define SEQ   1024
#define DMODEL 1024
#define HEADS 16
#define DK    64

// Scratch (device globals: allocation-free rule)
__device__ float g_Q[BATCH * HEADS * SEQ * DK];   // [b,h,n,d]  tf32-rounded, d pi-permuted
__device__ float g_K[BATCH * HEADS * SEQ * DK];
__device__ float g_V[BATCH * HEADS * SEQ * DK];
__device__ float g_O[BATCH * SEQ * DMODEL];       // [b,n,D] attention output (tf32-rounded)
__device__ float g_Xr[BATCH * SEQ * DMODEL];      // X rounded to tf32
__device__ float g_Wr[4 * DMODEL * DMODEL];       // Wq,Wk,Wv,Wo rounded to tf32

// ---------------------------------------------------------------------------
// tf32 + cp.async helpers
// ---------------------------------------------------------------------------
__device__ __forceinline__ unsigned int f2tf32(float x) {
    unsigned int u;
    asm("cvt.rna.tf32.f32 %0, %1;" : "=r"(u) : "f"(x));
    return u;
}
__device__ __forceinline__ float tf32f(float x) {
    return __uint_as_float(f2tf32(x));
}

__device__ __forceinline__ void mma_tf32(float c[4],
                                         unsigned int a0, unsigned int a1,
                                         unsigned int a2, unsigned int a3,
                                         unsigned int b0, unsigned int b1) {
    asm volatile(
        "mma.sync.aligned.m16n8k8.row.col.f32.tf32.tf32.f32 "
        "{%0,%1,%2,%3}, {%4,%5,%6,%7}, {%8,%9}, {%0,%1,%2,%3};\n"
        : "+f"(c[0]), "+f"(c[1]), "+f"(c[2]), "+f"(c[3])
        : "r"(a0), "r"(a1), "r"(a2), "r"(a3), "r"(b0), "r"(b1));
}

__device__ __forceinline__ void cp16(void* smem_dst, const void* gsrc) {
    unsigned int s = (unsigned int)__cvta_generic_to_shared(smem_dst);
    asm volatile("cp.async.cg.shared.global [%0], [%1], 16;\n" :: "r"(s), "l"(gsrc));
}
#define CP_COMMIT() asm volatile("cp.async.commit_group;\n" ::)
#define CP_WAIT1()  asm volatile("cp.async.wait_group 1;\n" ::)

// ---------------------------------------------------------------------------
// Rounding kernels: X and W* -> tf32 once (staging becomes raw byte copy)
// ---------------------------------------------------------------------------
__global__ void round_x_kernel(const float* __restrict__ X) {
    int i = blockIdx.x * blockDim.x + threadIdx.x;
    float4 v = ((const float4*)X)[i];
    v.x = tf32f(v.x); v.y = tf32f(v.y); v.z = tf32f(v.z); v.w = tf32f(v.w);
    ((float4*)g_Xr)[i] = v;
}

__global__ void round_w_kernel(const float* __restrict__ w0, const float* __restrict__ w1,
                               const float* __restrict__ w2, const float* __restrict__ w3) {
    int i = blockIdx.x * blockDim.x + threadIdx.x;
    int sel = i >> 18;
    int off = i & 262143;
    const float* src = (sel == 0) ? w0 : (sel == 1) ? w1 : (sel == 2) ? w2 : w3;
    float4 v = ((const float4*)src)[off];
    v.x = tf32f(v.x); v.y = tf32f(v.y); v.z = tf32f(v.z); v.w = tf32f(v.w);
    ((float4*)g_Wr)[i] = v;
}

// ---------------------------------------------------------------------------
// tf32 GEMM v3 (unchanged from R15, which passed): TBK=32, 2-stage cp.async,
// QKV fusion over blockIdx.z, dynamic smem.
// ---------------------------------------------------------------------------
#define TBM 128
#define TBN 128
#define TBK 32
#define AST 36
#define BST 136
#define GAS (TBM * AST)
#define GBS (TBK * BST)
#define GEMM_SMEM_BYTES ((2 * GAS + 2 * GBS) * 4)   // 71680 B

__global__ __launch_bounds__(256, 2)
void tf32_gemm3_kernel(const float* __restrict__ A,
                       const float* __restrict__ Wbase,
                       const float* __restrict__ bias0,
                       const float* __restrict__ bias1,
                       const float* __restrict__ bias2,
                       float* __restrict__ out,
                       int qkvMode)
{
    extern __shared__ __align__(16) float gsm[];
    float* AsB = gsm;
    float* BsB = gsm + 2 * GAS;

    const int z  = blockIdx.z;
    const float* W    = Wbase + (size_t)z * DMODEL * DMODEL;
    const float* bias = (z == 0) ? bias0 : (z == 1) ? bias1 : bias2;

    const int m0 = blockIdx.y * TBM;
    const int n0 = blockIdx.x * TBN;
    const int tid = threadIdx.x;
    const int wid = tid >> 5;
    const int lane = tid & 31;
    const int wm = wid >> 2;
    const int wn = wid & 3;
    const int gid = lane >> 2;
    const int tig = lane & 3;

    float c[4][4][4];
#pragma unroll
    for (int i = 0; i < 4; i++)
#pragma unroll
        for (int j = 0; j < 4; j++)
#pragma unroll
            for (int r = 0; r < 4; r++) c[i][j][r] = 0.0f;

#define GEMM_STAGE(buf, tidx) do {                                             \
        int k0s = (tidx) * TBK;                                                \
        float* Asb = AsB + (buf) * GAS;                                        \
        float* Bsb = BsB + (buf) * GBS;                                        \
        _Pragma("unroll")                                                      \
        for (int q = 0; q < 4; q++) {                                          \
            int cch = q * 256 + tid;                                           \
            int row = cch >> 3, sg = (cch & 7) << 2;                           \
            cp16(&Asb[row * AST + sg],                                         \
                 A + (size_t)(m0 + row) * DMODEL + k0s + sg);                  \
        }                                                                      \
        _Pragma("unroll")                                                      \
        for (int q = 0; q < 4; q++) {                                          \
            int cch = q * 256 + tid;                                           \
            int kk = cch >> 5, cs = (cch & 31) << 2;                           \
            cp16(&Bsb[kk * BST + cs],                                          \
                 W + (size_t)(k0s + kk) * DMODEL + n0 + cs);                   \
        }                                                                      \
    } while (0)

    GEMM_STAGE(0, 0);
    CP_COMMIT();

    for (int t = 0; t < DMODEL / TBK; t++) {
        int buf = t & 1;
        if (t < DMODEL / TBK - 1) GEMM_STAGE(buf ^ 1, t + 1);
        CP_COMMIT();
        CP_WAIT1();
        __syncthreads();

        const float* Asb = AsB + buf * GAS;
        const float* Bsb = BsB + buf * GBS;

#pragma unroll
        for (int ks = 0; ks < 4; ks++) {
            const int kb = ks * 8;
            unsigned int af[4][4], bf[4][2];
#pragma unroll
            for (int i = 0; i < 4; i++) {
                int mb = wm * 64 + i * 16;
                af[i][0] = __float_as_uint(Asb[(mb + gid    ) * AST + kb + tig]);
                af[i][1] = __float_as_uint(Asb[(mb + gid + 8) * AST + kb + tig]);
                af[i][2] = __float_as_uint(Asb[(mb + gid    ) * AST + kb + tig + 4]);
                af[i][3] = __float_as_uint(Asb[(mb + gid + 8) * AST + kb + tig + 4]);
            }
#pragma unroll
            for (int j = 0; j < 4; j++) {
                int nb = wn * 32 + j * 8;
                bf[j][0] = __float_as_uint(Bsb[(kb + tig    ) * BST + nb + gid]);
                bf[j][1] = __float_as_uint(Bsb[(kb + tig + 4) * BST + nb + gid]);
            }
#pragma unroll
            for (int i = 0; i < 4; i++)
#pragma unroll
                for (int j = 0; j < 4; j++)
                    mma_tf32(c[i][j], af[i][0], af[i][1], af[i][2], af[i][3],
                             bf[j][0], bf[j][1]);
        }
        __syncthreads();
    }
#undef GEMM_STAGE

    float* dst = out;
    if (qkvMode) dst = (z == 0) ? g_Q : (z == 1) ? g_K : g_V;

#pragma unroll
    for (int i = 0; i < 4; i++) {
        int r0 = m0 + wm * 64 + i * 16 + gid;
        int r1 = r0 + 8;
#pragma unroll
        for (int j = 0; j < 4; j++) {
            int cb = n0 + wn * 32 + j * 8 + 2 * tig;
#pragma unroll
            for (int e = 0; e < 2; e++) {
                int cc = cb + e;
                float v0 = c[i][j][e]     + bias[cc];
                float v1 = c[i][j][e + 2] + bias[cc];
                if (qkvMode) {
                    int h = cc >> 6, d = cc & 63;
                    int d2 = (d & 56) | (2 * (d & 3) + ((d & 7) >> 2));
                    int b0i = r0 >> 10, n0i = r0 & 1023;
                    int b1i = r1 >> 10, n1i = r1 & 1023;
                    dst[(size_t)(b0i * HEADS + h) * (SEQ * DK) + (size_t)n0i * DK + d2] = tf32f(v0);
                    dst[(size_t)(b1i * HEADS + h) * (SEQ * DK) + (size_t)n1i * DK + d2] = tf32f(v1);
                } else {
                    dst[(size_t)r0 * DMODEL + cc] = v0;
                    dst[(size_t)r1 * DMODEL + cc] = v1;
                }
            }
        }
    }
}

// ---------------------------------------------------------------------------
// Tensor-core flash attention v5: 256 threads, 8 warps as 8(m) x 1(n).
// Warp tile 16q x 64k: each warp owns 16 FULL rows -> softmax is quad-local
// (2 shfl.xor), no cross-warp exchange, no sMax/sSum smem, and only TWO
// __syncthreads per tile (pipeline wait + buffer release).
// ---------------------------------------------------------------------------
#define AT 72
#define SQ_OFF   0
#define SK_OFF   (128 * AT)
#define SV_OFF   (SK_OFF + 2 * 64 * AT)
#define SP_OFF   (SV_OFF + 2 * 64 * AT)
#define SMSK_OFF (SP_OFF + 2 * 128 * AT)
#define ATTN_SMEM_BYTES ((SMSK_OFF + 1024) * 4)   // 190464 B

__global__ __launch_bounds__(256, 1)
void attn_tc5_kernel(const float* __restrict__ Bij,
                     const unsigned int* __restrict__ maskW)
{
    extern __shared__ float sm[];
    unsigned int* sMsk = (unsigned int*)(sm + SMSK_OFF);

    const int b  = blockIdx.z;
    const int h  = blockIdx.y;
    const int q0 = blockIdx.x * 128;
    const int tid  = threadIdx.x;
    const int lane = tid & 31;
    const int wid  = tid >> 5;        // warp = m block (0..7)
    const int gid = lane >> 2;        // 0..7
    const int tig = lane & 3;         // 0..3
    const int bh = b * HEADS + h;
    const float scale = 0.125f;

    const int pg  = 2 * (gid & 3) + (gid >> 2);
    const int pu0 = 2 * ((2 * tig) & 3) + ((2 * tig) >> 2);
    const int pu1 = 2 * ((2 * tig + 1) & 3) + ((2 * tig + 1) >> 2);

    const int r0 = wid * 16 + gid;    // thread's 2 q-rows
    const int r1 = r0 + 8;

    const float* Qg = g_Q + (size_t)(bh * SEQ + q0) * DK;
    const float* Kg = g_K + (size_t)bh * SEQ * DK;
    const float* Vg = g_V + (size_t)bh * SEQ * DK;
    const float* Bg = Bij + ((size_t)bh * SEQ + q0) * SEQ;

#define ATTN_STAGE(buf, kt) do {                                               \
        float* sKb = sm + SK_OFF + (buf) * 64 * AT;                            \
        float* sVb = sm + SV_OFF + (buf) * 64 * AT;                            \
        float* sPb = sm + SP_OFF + (buf) * 128 * AT;                           \
        const float* Kt = Kg + (size_t)(kt) * 64 * DK;                         \
        const float* Vt = Vg + (size_t)(kt) * 64 * DK;                         \
        const float* Bt = Bg + (kt) * 64;                                      \
        _Pragma("unroll")                                                      \
        for (int t = 0; t < 4; t++) {                                          \
            int cch = t * 256 + tid;                                           \
            int row = cch >> 4, col = (cch & 15) << 2;                         \
            cp16(&sKb[row * AT + col], Kt + row * DK + col);                   \
            cp16(&sVb[row * AT + col], Vt + row * DK + col);                   \
        }                                                                      \
        _Pragma("unroll")                                                      \
        for (int t = 0; t < 8; t++) {                                          \
            int cch = t * 256 + tid;                                           \
            int row = cch >> 4, col = (cch & 15) << 2;                         \
            cp16(&sPb[row * AT + col], Bt + (size_t)row * SEQ + col);          \
        }                                                                      \
    } while (0)

    // Prologue: Q (128x64), mask (1024 words), tile 0
    {
#pragma unroll
        for (int t = 0; t < 8; t++) {
            int cch = t * 256 + tid;
            int row = cch >> 4, col = (cch & 15) << 2;
            cp16(&sm[SQ_OFF + row * AT + col], Qg + (size_t)row * DK + col);
        }
        cp16(&sMsk[tid * 4], maskW + (size_t)b * SEQ + tid * 4);
        ATTN_STAGE(0, 0);
        CP_COMMIT();
    }

    float mI0 = -INFINITY, mI1 = -INFINITY, lI0 = 0.0f, lI1 = 0.0f;
    float o[8][4];
#pragma unroll
    for (int j = 0; j < 8; j++)
#pragma unroll
        for (int r = 0; r < 4; r++) o[j][r] = 0.0f;

    for (int kt = 0; kt < SEQ / 64; kt++) {
        const int buf = kt & 1;
        const int k0c = kt * 64;
        float* sKb = sm + SK_OFF + buf * 64 * AT;
        float* sVb = sm + SV_OFF + buf * 64 * AT;
        float* sPb = sm + SP_OFF + buf * 128 * AT;

        if (kt + 1 < SEQ / 64) ATTN_STAGE(buf ^ 1, kt + 1);
        CP_COMMIT();
        CP_WAIT1();
        __syncthreads();   // staged K/V/bias visible to all warps

        // ---- S = Q K^T : warp 16x64, c[8][4] ----
        float c[8][4];
#pragma unroll
        for (int j = 0; j < 8; j++)
#pragma unroll
            for (int r = 0; r < 4; r++) c[j][r] = 0.0f;

#pragma unroll
        for (int kb = 0; kb < 64; kb += 8) {
            float2 qa0 = *(float2*)&sm[SQ_OFF + r0 * AT + kb + 2 * tig];
            float2 qa1 = *(float2*)&sm[SQ_OFF + r1 * AT + kb + 2 * tig];
            unsigned int a0 = __float_as_uint(qa0.x);
            unsigned int a1 = __float_as_uint(qa1.x);
            unsigned int a2 = __float_as_uint(qa0.y);
            unsigned int a3 = __float_as_uint(qa1.y);
#pragma unroll
            for (int j = 0; j < 8; j++) {
                float2 kf = *(float2*)&sKb[(j * 8 + gid) * AT + kb + 2 * tig];
                mma_tf32(c[j], a0, a1, a2, a3,
                         __float_as_uint(kf.x), __float_as_uint(kf.y));
            }
        }

        // ---- scale + bias + mask; quad-local row max ----
        float pm0 = -INFINITY, pm1 = -INFINITY;
#pragma unroll
        for (int j = 0; j < 8; j++) {
            int cc0 = j * 8 + 2 * tig;
            int cc1 = cc0 + 1;
            bool mk0 = sMsk[k0c + cc0] != 0u;
            bool mk1 = sMsk[k0c + cc1] != 0u;
            float v0 = mk0 ? fmaf(c[j][0], scale, sPb[r0 * AT + cc0]) : -10000.0f;
            float v1 = mk1 ? fmaf(c[j][1], scale, sPb[r0 * AT + cc1]) : -10000.0f;
            float v2 = mk0 ? fmaf(c[j][2], scale, sPb[r1 * AT + cc0]) : -10000.0f;
            float v3 = mk1 ? fmaf(c[j][3], scale, sPb[r1 * AT + cc1]) : -10000.0f;
            c[j][0] = v0; c[j][1] = v1; c[j][2] = v2; c[j][3] = v3;
            pm0 = fmaxf(pm0, fmaxf(v0, v1));
            pm1 = fmaxf(pm1, fmaxf(v2, v3));
        }
        pm0 = fmaxf(pm0, __shfl_xor_sync(0xffffffffu, pm0, 1));
        pm0 = fmaxf(pm0, __shfl_xor_sync(0xffffffffu, pm0, 2));
        pm1 = fmaxf(pm1, __shfl_xor_sync(0xffffffffu, pm1, 1));
        pm1 = fmaxf(pm1, __shfl_xor_sync(0xffffffffu, pm1, 2));

        float mN0 = fmaxf(mI0, pm0);
        float mN1 = fmaxf(mI1, pm1);
        float al0 = __expf(mI0 - mN0);
        float al1 = __expf(mI1 - mN1);
        mI0 = mN0; mI1 = mN1;

        // exp + write P (tf32, pi cols) into OWN rows (no barrier needed)
        float ps0 = 0.0f, ps1 = 0.0f;
#pragma unroll
        for (int j = 0; j < 8; j++) {
            int base0 = r0 * AT + j * 8;
            int base1 = r1 * AT + j * 8;
            float p0 = __expf(c[j][0] - mN0);
            float p1 = __expf(c[j][1] - mN0);
            float p2 = __expf(c[j][2] - mN1);
            float p3 = __expf(c[j][3] - mN1);
            sPb[base0 + pu0] = tf32f(p0);
            sPb[base0 + pu1] = tf32f(p1);
            sPb[base1 + pu0] = tf32f(p2);
            sPb[base1 + pu1] = tf32f(p3);
            ps0 += p0 + p1;
            ps1 += p2 + p3;
        }
        ps0 += __shfl_xor_sync(0xffffffffu, ps0, 1);
        ps0 += __shfl_xor_sync(0xffffffffu, ps0, 2);
        ps1 += __shfl_xor_sync(0xffffffffu, ps1, 1);
        ps1 += __shfl_xor_sync(0xffffffffu, ps1, 2);
        lI0 = lI0 * al0 + ps0;
        lI1 = lI1 * al1 + ps1;

        // rescale O accumulators
#pragma unroll
        for (int j = 0; j < 8; j++) {
            o[j][0] *= al0; o[j][1] *= al0;
            o[j][2] *= al1; o[j][3] *= al1;
        }

        // ---- O += P V  (A-frags from own P rows; same-warp, no barrier) ----
#pragma unroll
        for (int kb = 0; kb < 64; kb += 8) {
            float2 pa0 = *(float2*)&sPb[r0 * AT + kb + 2 * tig];
            float2 pa1 = *(float2*)&sPb[r1 * AT + kb + 2 * tig];
            unsigned int a0 = __float_as_uint(pa0.x);
            unsigned int a1 = __float_as_uint(pa1.x);
            unsigned int a2 = __float_as_uint(pa0.y);
            unsigned int a3 = __float_as_uint(pa1.y);
#pragma unroll
            for (int j = 0; j < 8; j++) {
                int dcol = j * 8 + pg;
                unsigned int b0 = __float_as_uint(sVb[(kb + tig)     * AT + dcol]);
                unsigned int b1 = __float_as_uint(sVb[(kb + tig + 4) * AT + dcol]);
                mma_tf32(o[j], a0, a1, a2, a3, b0, b1);
            }
        }
        __syncthreads();   // all warps done with buf before next prefetch overwrites it
    }
#undef ATTN_STAGE

    // Epilogue: write [b, q0+row, h*64 + d], tf32-rounded for final GEMM
    float inv0 = 1.0f / lI0;
    float inv1 = 1.0f / lI1;
    float* Og = g_O + ((size_t)b * SEQ + q0) * DMODEL + h * DK;
#pragma unroll
    for (int j = 0; j < 8; j++) {
#pragma unroll
        for (int e = 0; e < 2; e++) {
            int cc = j * 8 + 2 * tig + e;
            Og[(size_t)r0 * DMODEL + cc] = tf32f(o[j][e]     * inv0);
            Og[(size_t)r1 * DMODEL + cc] = tf32f(o[j][e + 2] * inv1);
        }
    }
}

// ---------------------------------------------------------------------------
extern "C" void kernel_launch(void* const* d_in, const int* in_sizes, int n_in,
                              void* d_out, int out_size)
{
    // Identify inputs by element count (robust to metadata ordering)
    const float* X = 0; const float* Bij = 0; const void* maskP = 0;
    const float* Ws[4] = {0, 0, 0, 0};
    const float* bs[4] = {0, 0, 0, 0};
    int nW = 0, nB = 0;
    for (int i = 0; i < n_in; i++) {
        int sz = in_sizes[i];
        if (sz == BATCH * HEADS * SEQ * SEQ)      Bij  = (const float*)d_in[i];
        else if (sz == BATCH * SEQ * DMODEL)      X    = (const float*)d_in[i];
        else if (sz == BATCH * SEQ)               maskP = d_in[i];
        else if (sz == DMODEL * DMODEL && nW < 4) Ws[nW++] = (const float*)d_in[i];
        else if (sz == DMODEL && nB < 4)          bs[nB++] = (const float*)d_in[i];
    }
    const float *Wq = Ws[0], *Wk = Ws[1], *Wv = Ws[2], *Wo = Ws[3];
    const float *bq = bs[0], *bk = bs[1], *bv = bs[2], *bo = bs[3];
    float* out = (float*)d_out;

    float *op, *xr, *wr;
    cudaGetSymbolAddress((void**)&op, g_O);
    cudaGetSymbolAddress((void**)&xr, g_Xr);
    cudaGetSymbolAddress((void**)&wr, g_Wr);

    cudaFuncSetAttribute(attn_tc5_kernel, cudaFuncAttributeMaxDynamicSharedMemorySize,
                         ATTN_SMEM_BYTES);
    cudaFuncSetAttribute(tf32_gemm3_kernel, cudaFuncAttributeMaxDynamicSharedMemorySize,
                         GEMM_SMEM_BYTES);

    // Pre-round X and weights to tf32
    round_x_kernel<<<4096, 256>>>(X);
    round_w_kernel<<<4096, 256>>>(Wq, Wk, Wv, Wo);

    const int WSZ = DMODEL * DMODEL;

    // Fused QKV: grid.z = 3 selects W/bias/destination
    dim3 gQKV(DMODEL / TBN, (BATCH * SEQ) / TBM, 3);   // (8, 32, 3)
    tf32_gemm3_kernel<<<gQKV, 256, GEMM_SMEM_BYTES>>>(xr, wr, bq, bk, bv, 0, 1);

    dim3 gAttn(SEQ / 128, HEADS, BATCH);               // (8, 16, 4)
    attn_tc5_kernel<<<gAttn, 256, ATTN_SMEM_BYTES>>>(Bij, (const unsigned int*)maskP);

    // Output projection (z=0 only)
    dim3 gO(DMODEL / TBN, (BATCH * SEQ) / TBM, 1);
    tf32_gemm3_kernel<<<gO, 256, GEMM_SMEM_BYTES>>>(op, wr + 3 * WSZ, bo, bo, bo, out, 0);
}